// round 13
// baseline (speedup 1.0000x reference)
#include <cuda_runtime.h>
#include <cuda_fp16.h>
#include <math.h>
#include <stdint.h>

#define Nn 32768
#define Gg 256
#define Ee 262144

typedef __half hf;

// ---------------- scratch (device globals: no allocation) ----------------
__device__ float g_deg[Nn];
__device__ float g_dinv[Nn];
__device__ float g_ahat[Gg * 16384];
__device__ float g_acc[Gg * 2];
__device__ int   g_is64;

#define DECLHF(n, sz) __device__ __align__(16) hf n[sz]
DECLHF(g_X,  Nn * 256);
DECLHF(g_Pa, Nn * 256);
DECLHF(g_Px, Nn * 256);
DECLHF(g_Aca, Nn * 256);
DECLHF(g_Acx, Nn * 256);
DECLHF(g_Af, Nn * 256);
DECLHF(g_Xf, Nn * 256);
DECLHF(g_Ah, Gg * 16384);
DECLHF(g_Wt, 4 * 65536);

__device__ __forceinline__ hf* bufsel(int id) {
    switch (id) {
        case 0: return g_X;   case 1: return g_Pa; case 2: return g_Px;
        case 3: return g_Aca; case 4: return g_Acx;
        case 5: return g_Af;  case 6: return g_Xf; case 7: return g_Ah;
    }
    return g_Wt + (-id - 1) * 65536;
}

// ---------------- mma.sync m16n8k16 fp16 ----------------
__device__ __forceinline__ void mma16816(float* c, const uint32_t* a, const uint32_t* b) {
    asm volatile(
        "mma.sync.aligned.m16n8k16.row.col.f32.f16.f16.f32 "
        "{%0,%1,%2,%3}, {%4,%5,%6,%7}, {%8,%9}, {%0,%1,%2,%3};"
        : "+f"(c[0]), "+f"(c[1]), "+f"(c[2]), "+f"(c[3])
        : "r"(a[0]), "r"(a[1]), "r"(a[2]), "r"(a[3]), "r"(b[0]), "r"(b[1]));
}
__device__ __forceinline__ void ldsm4(uint32_t* r, uint32_t addr) {
    asm volatile("ldmatrix.sync.aligned.m8n8.x4.shared.b16 {%0,%1,%2,%3}, [%4];"
        : "=r"(r[0]), "=r"(r[1]), "=r"(r[2]), "=r"(r[3]) : "r"(addr));
}
#define CPA16(dst, src) asm volatile("cp.async.cg.shared.global [%0], [%1], 16;" :: "r"(dst), "l"(src) : "memory")
#define CPA_COMMIT()    asm volatile("cp.async.commit_group;" ::: "memory")
#define CPA_WAIT1()     asm volatile("cp.async.wait_group 1;" ::: "memory")
#define CPA_WAIT0()     asm volatile("cp.async.wait_group 0;" ::: "memory")

// ---------------- structure kernels (fused) ----------------
__device__ __forceinline__ int edge_elem(const int* __restrict__ ei32, int i) {
    return g_is64 ? ei32[2 * i] : ei32[i];
}
__global__ void k_init(const int* __restrict__ ei32) {
    int i = blockIdx.x * blockDim.x + threadIdx.x;
    if (i == 0) {
        int any = 0;
        for (int k = 0; k < 128; k++) any |= ei32[2 * k + 1];
        g_is64 = (any == 0) ? 1 : 0;
    }
    int stride = gridDim.x * blockDim.x;
    for (int j = i; j < Gg * 16384; j += stride) g_ahat[j] = 0.f;
    if (i < Nn) g_deg[i] = 0.f;
    if (i < Gg * 2) g_acc[i] = 0.f;
}
__global__ void k_deg(const int* __restrict__ ei32) {
    int e = blockIdx.x * blockDim.x + threadIdx.x;
    if (e < Ee) {
        int d = edge_elem(ei32, Ee + e);
        if ((unsigned)d < Nn) atomicAdd(&g_deg[d], 1.f);
    }
}
__global__ void k_dinv() {
    int i = blockIdx.x * blockDim.x + threadIdx.x;
    if (i < Nn) g_dinv[i] = rsqrtf(g_deg[i] + 1.f);
}
__global__ void k_scatter(const int* __restrict__ ei32) {
    int idx = blockIdx.x * blockDim.x + threadIdx.x;
    if (idx < Ee) {
        int s = edge_elem(ei32, idx);
        int d = edge_elem(ei32, Ee + idx);
        if ((unsigned)s < Nn && (unsigned)d < Nn) {
            int g = d >> 7;
            atomicAdd(&g_ahat[(g << 14) + ((d & 127) << 7) + (s & 127)],
                      g_dinv[s] * g_dinv[d]);
        }
    } else {
        int i = idx - Ee;
        if (i < Nn) {
            int g = i >> 7, l = i & 127;
            atomicAdd(&g_ahat[(g << 14) + l * 128 + l], g_dinv[i] * g_dinv[i]);
        }
    }
}
// fused converts: ahat -> fp16, X -> fp16, all 4 weight transposes
__global__ void k_split_all(const float* __restrict__ x,
                            const float* __restrict__ W0, const float* __restrict__ W1,
                            const float* __restrict__ W2, const float* __restrict__ W3) {
    int i = blockIdx.x * blockDim.x + threadIdx.x;
    int stride = gridDim.x * blockDim.x;
    for (int j = i; j < Gg * 16384; j += stride)
        g_Ah[j] = __float2half_rn(g_ahat[j]);
    for (int j = i; j < Nn * 256; j += stride)
        g_X[j] = __float2half_rn(x[j]);
    for (int j = i; j < 4 * 65536; j += stride) {
        int w = j >> 16, r = j & 65535;
        int n = r >> 8, k = r & 255;
        const float* W = w == 0 ? W0 : (w == 1 ? W1 : (w == 2 ? W2 : W3));
        g_Wt[j] = __float2half_rn(W[k * 256 + n]);   // Wt[n][k] = W[k][n]
    }
}

// ---------------- pipelined mma GEMM (single-pass fp16, K-chunk 64) ----------------
struct GArg { int aid, bid, oid; const float* bias; int relu; };

#define ST_ROW 144          // 64 halves (128B) + 16B pad; ldsm conflict-free (4*row mod 32)
#define ST_ARR 18432        // 128 * 144
#define ST_STAGE 36864      // A + B
#define SMEM_BYTES (2 * ST_STAGE)

template <int MODE>
__global__ void __launch_bounds__(256, 2) k_mma(GArg pA, GArg pB,
                                                int aG, int lda, int bG, int ldb, int oG,
                                                const float* __restrict__ Wl) {
    constexpr int KK = (MODE == 0) ? 256 : 128;
    constexpr int NCH = KK / 64;
    extern __shared__ __align__(16) char dynsm[];
    const uint32_t smbase = (uint32_t)__cvta_generic_to_shared(dynsm);

    const int t = threadIdx.x, lane = t & 31, wid = t >> 5;
    const int wr = wid >> 1, wc = wid & 1;
    const int g = blockIdx.x;
    int mb, nb, path;
    if (MODE == 1)      { mb = 0; path = blockIdx.y; nb = blockIdx.z; }
    else if (MODE == 3) { mb = blockIdx.y; nb = blockIdx.z; path = 0; }
    else                { mb = blockIdx.y; path = blockIdx.z; nb = 0; }
    const GArg P = path ? pB : pA;

    const hf* A = bufsel(P.aid) + g * aG + mb * 128 * lda;
    const hf* B = bufsel(P.bid) + g * bG + nb * 128 * ldb;

    const int ldrow = t >> 1, ldsegb = (t & 1) * 4;   // row 0..127, 4 16B-segs per half-row
    auto issue = [&](int ch) {
        uint32_t sb = smbase + (ch & 1) * ST_STAGE;
        uint32_t dro = ldrow * ST_ROW + ldsegb * 16;
        const hf* ap = A + ldrow * lda + ch * 64 + ldsegb * 8;
        const hf* bp = B + ldrow * ldb + ch * 64 + ldsegb * 8;
#pragma unroll
        for (int sgi = 0; sgi < 4; sgi++) {
            CPA16(sb + dro + sgi * 16,          ap + sgi * 8);
            CPA16(sb + ST_ARR + dro + sgi * 16, bp + sgi * 8);
        }
        CPA_COMMIT();
    };

    float acc[2][8][4];
#pragma unroll
    for (int i = 0; i < 2; i++)
#pragma unroll
        for (int j = 0; j < 8; j++)
#pragma unroll
            for (int q = 0; q < 4; q++) acc[i][j][q] = 0.f;

    issue(0);
    const int atile = lane >> 3, arow = lane & 7;
    for (int ch = 0; ch < NCH; ch++) {
        if (ch + 1 < NCH) { issue(ch + 1); CPA_WAIT1(); } else { CPA_WAIT0(); }
        __syncthreads();
        uint32_t sb = smbase + (ch & 1) * ST_STAGE;
#pragma unroll
        for (int ks = 0; ks < 4; ks++) {
            const int k0b = ks * 32;
            uint32_t ah[8];
#pragma unroll
            for (int mt = 0; mt < 2; mt++) {
                uint32_t addr = sb + (wr * 32 + mt * 16 + ((atile & 1) << 3) + arow) * ST_ROW
                                + k0b + ((atile >> 1) << 4);
                ldsm4(ah + mt * 4, addr);
            }
#pragma unroll
            for (int ntp = 0; ntp < 4; ntp++) {
                uint32_t baddr = sb + ST_ARR
                                 + (wc * 64 + ntp * 16 + ((atile >> 1) << 3) + arow) * ST_ROW
                                 + k0b + ((atile & 1) << 4);
                uint32_t bh2[4];
                ldsm4(bh2, baddr);
#pragma unroll
                for (int q2 = 0; q2 < 2; q2++) {
                    int nt = ntp * 2 + q2;
#pragma unroll
                    for (int mt = 0; mt < 2; mt++)
                        mma16816(acc[mt][nt], ah + mt * 4, bh2 + q2 * 2);
                }
            }
        }
        __syncthreads();
    }

    const int gi = lane >> 2, tg = lane & 3;
    // ---------------- epilogues ----------------
    if (MODE == 3) {
        float c0 = 0.f, c1 = 0.f;
        const float2* W2 = (const float2*)Wl;
#pragma unroll
        for (int mt = 0; mt < 2; mt++)
#pragma unroll
            for (int nt = 0; nt < 8; nt++) {
                int d0 = mb * 128 + wr * 32 + mt * 16 + gi;
                int e  = nb * 128 + wc * 64 + nt * 8 + tg * 2;
                float2 w;
                w = __ldg(&W2[d0 * 256 + e]);           c0 += acc[mt][nt][0] * w.x; c1 += acc[mt][nt][0] * w.y;
                w = __ldg(&W2[d0 * 256 + e + 1]);       c0 += acc[mt][nt][1] * w.x; c1 += acc[mt][nt][1] * w.y;
                w = __ldg(&W2[(d0 + 8) * 256 + e]);     c0 += acc[mt][nt][2] * w.x; c1 += acc[mt][nt][2] * w.y;
                w = __ldg(&W2[(d0 + 8) * 256 + e + 1]); c0 += acc[mt][nt][3] * w.x; c1 += acc[mt][nt][3] * w.y;
            }
        float* red = (float*)dynsm;
        red[t] = c0; __syncthreads();
        for (int s = 128; s > 0; s >>= 1) { if (t < s) red[t] += red[t + s]; __syncthreads(); }
        if (t == 0) atomicAdd(&g_acc[g * 2], red[0]);
        __syncthreads();
        red[t] = c1; __syncthreads();
        for (int s = 128; s > 0; s >>= 1) { if (t < s) red[t] += red[t + s]; __syncthreads(); }
        if (t == 0) atomicAdd(&g_acc[g * 2 + 1], red[0]);
        return;
    }

    hf* O;
    int ostride, ocol0;
    if (MODE == 1) { O = bufsel(P.oid) + g * oG; ostride = 256; ocol0 = nb * 128; }
    else           { O = bufsel(P.oid) + g * oG + mb * 16384; ostride = 128; ocol0 = 0; }

#pragma unroll
    for (int mt = 0; mt < 2; mt++)
#pragma unroll
        for (int nt = 0; nt < 8; nt++) {
            int row0 = wr * 32 + mt * 16 + gi;
            int col  = wc * 64 + nt * 8 + tg * 2;
#pragma unroll
            for (int half = 0; half < 2; half++) {
                int row = row0 + half * 8;
                float v0 = acc[mt][nt][half * 2];
                float v1 = acc[mt][nt][half * 2 + 1];
                if (MODE == 1) {
                    v0 += __ldg(&P.bias[ocol0 + col]);
                    v1 += __ldg(&P.bias[ocol0 + col + 1]);
                    if (P.relu) { v0 = fmaxf(v0, 0.f); v1 = fmaxf(v1, 0.f); }
                } else if (MODE == 2) {
                    float bb = __ldg(&P.bias[mb * 128 + row]);
                    v0 += bb; v1 += bb;
                    if (P.relu) { v0 = fmaxf(v0, 0.f); v1 = fmaxf(v1, 0.f); }
                }
                __half2 hp;
                hp.x = __float2half_rn(v0); hp.y = __float2half_rn(v1);
                *(__half2*)(O + row * ostride + ocol0 + col) = hp;
            }
        }
}

// ---------------- per-row softmax on the a2 feature-major plane (in-place) ----------------
__global__ void k_segsm2() {
    int w = threadIdx.x >> 5, l = threadIdx.x & 31;
    int row = blockIdx.x * 8 + w;
    hf* ph = g_Af + row * 128;
    float v[4];
#pragma unroll
    for (int i = 0; i < 4; i++) v[i] = __half2float(ph[l * 4 + i]);
    float m = fmaxf(fmaxf(v[0], v[1]), fmaxf(v[2], v[3]));
#pragma unroll
    for (int s = 16; s > 0; s >>= 1) m = fmaxf(m, __shfl_xor_sync(0xFFFFFFFF, m, s));
    float e[4], su = 0.f;
#pragma unroll
    for (int i = 0; i < 4; i++) { e[i] = __expf(v[i] - m); su += e[i]; }
#pragma unroll
    for (int s = 16; s > 0; s >>= 1) su += __shfl_xor_sync(0xFFFFFFFF, su, s);
    float inv = 1.f / su;
#pragma unroll
    for (int i = 0; i < 4; i++) ph[l * 4 + i] = __float2half_rn(e[i] * inv);
}

// ---------------- final bias + 2-class softmax ----------------
__global__ void k_final(const float* __restrict__ bl, float* __restrict__ out) {
    int g = blockIdx.x * blockDim.x + threadIdx.x;
    if (g < Gg) {
        float a = g_acc[2 * g] + bl[0];
        float b = g_acc[2 * g + 1] + bl[1];
        float m = fmaxf(a, b);
        float ea = __expf(a - m), eb = __expf(b - m);
        float inv = 1.f / (ea + eb);
        out[2 * g] = ea * inv;
        out[2 * g + 1] = eb * inv;
    }
}

// ---------------- launch ----------------
extern "C" void kernel_launch(void* const* d_in, const int* in_sizes, int n_in,
                              void* d_out, int out_size) {
    const float* x    = (const float*)d_in[0];
    const int*   ei32 = (const int*)d_in[1];
    const float* Wa1 = (const float*)d_in[3];
    const float* ba1 = (const float*)d_in[4];
    const float* Wa2 = (const float*)d_in[5];
    const float* ba2 = (const float*)d_in[6];
    const float* Wx1 = (const float*)d_in[7];
    const float* bx1 = (const float*)d_in[8];
    const float* Wx2 = (const float*)d_in[9];
    const float* bx2 = (const float*)d_in[10];
    const float* Wl  = (const float*)d_in[11];
    const float* bl  = (const float*)d_in[12];
    float* out = (float*)d_out;

    static int smem_set = 0;
    if (!smem_set) {
        cudaFuncSetAttribute(k_mma<0>, cudaFuncAttributeMaxDynamicSharedMemorySize, SMEM_BYTES);
        cudaFuncSetAttribute(k_mma<1>, cudaFuncAttributeMaxDynamicSharedMemorySize, SMEM_BYTES);
        cudaFuncSetAttribute(k_mma<2>, cudaFuncAttributeMaxDynamicSharedMemorySize, SMEM_BYTES);
        cudaFuncSetAttribute(k_mma<3>, cudaFuncAttributeMaxDynamicSharedMemorySize, SMEM_BYTES);
        smem_set = 1;
    }

    // structure (fused)
    k_init<<<128, 256>>>(ei32);
    k_deg<<<Ee / 256, 256>>>(ei32);
    k_dinv<<<Nn / 256, 256>>>();
    k_scatter<<<(Ee + Nn) / 256, 256>>>(ei32);

    // converts (single fused kernel)
    k_split_all<<<4096, 256>>>(x, Wa1, Wa2, Wx1, Wx2);

    // ids: 0=X 1=Pa 2=Px 3=Aca 4=Acx 5=Af 6=Xf 7=Ahat; neg = Wt(-1..-4)
    dim3 gq(Gg, 2, 2);
    GArg pa, pb;

    // layer-1 feature GEMMs (both paths)
    pa = {-1, 0, 1, nullptr, 0}; pb = {-3, 0, 2, nullptr, 0};
    k_mma<0><<<gq, 256, SMEM_BYTES>>>(pa, pb, 0, 256, 32768, 256, 32768, nullptr);
    // layer-1 propagation (both paths)
    pa = {7, 1, 3, ba1, 1}; pb = {7, 2, 4, bx1, 1};
    k_mma<1><<<gq, 256, SMEM_BYTES>>>(pa, pb, 16384, 128, 32768, 128, 32768, nullptr);
    // layer-2 feature GEMMs
    pa = {-2, 3, 1, nullptr, 0}; pb = {-4, 4, 2, nullptr, 0};
    k_mma<0><<<gq, 256, SMEM_BYTES>>>(pa, pb, 0, 256, 32768, 256, 32768, nullptr);
    // layer-2 propagation (transposed)
    pa = {1, 7, 5, ba2, 0}; pb = {2, 7, 6, bx2, 1};
    k_mma<2><<<gq, 256, SMEM_BYTES>>>(pa, pb, 32768, 128, 16384, 128, 32768, nullptr);

    k_segsm2<<<8192, 256>>>();

    // bilinear + head
    pa = {5, 6, 0, nullptr, 0};
    k_mma<3><<<gq, 256, SMEM_BYTES>>>(pa, pa, 32768, 128, 32768, 128, 0, Wl);
    k_final<<<1, 256>>>(bl, out);
}

// round 14
// speedup vs baseline: 1.1284x; 1.1284x over previous
#include <cuda_runtime.h>
#include <cuda_fp16.h>
#include <math.h>
#include <stdint.h>

#define Nn 32768
#define Gg 256
#define Ee 262144

typedef __half hf;

// ---------------- scratch (device globals: no allocation) ----------------
__device__ float g_deg[Nn];
__device__ float g_dinv[Nn];
__device__ float g_ahat[Gg * 16384];
__device__ float g_acc[Gg * 2];
__device__ int   g_is64;

#define DECLHF(n, sz) __device__ __align__(16) hf n[sz]
DECLHF(g_X,  Nn * 256);
DECLHF(g_Pa, Nn * 256);
DECLHF(g_Px, Nn * 256);
DECLHF(g_Aca, Nn * 256);
DECLHF(g_Acx, Nn * 256);
DECLHF(g_Af, Nn * 256);
DECLHF(g_Xf, Nn * 256);
DECLHF(g_Ah, Gg * 16384);
DECLHF(g_Wt, 4 * 65536);

__device__ __forceinline__ hf* bufsel(int id) {
    switch (id) {
        case 0: return g_X;   case 1: return g_Pa; case 2: return g_Px;
        case 3: return g_Aca; case 4: return g_Acx;
        case 5: return g_Af;  case 6: return g_Xf; case 7: return g_Ah;
    }
    return g_Wt + (-id - 1) * 65536;
}

// ---------------- mma.sync m16n8k16 fp16 ----------------
__device__ __forceinline__ void mma16816(float* c, const uint32_t* a, const uint32_t* b) {
    asm volatile(
        "mma.sync.aligned.m16n8k16.row.col.f32.f16.f16.f32 "
        "{%0,%1,%2,%3}, {%4,%5,%6,%7}, {%8,%9}, {%0,%1,%2,%3};"
        : "+f"(c[0]), "+f"(c[1]), "+f"(c[2]), "+f"(c[3])
        : "r"(a[0]), "r"(a[1]), "r"(a[2]), "r"(a[3]), "r"(b[0]), "r"(b[1]));
}
__device__ __forceinline__ void ldsm4(uint32_t* r, uint32_t addr) {
    asm volatile("ldmatrix.sync.aligned.m8n8.x4.shared.b16 {%0,%1,%2,%3}, [%4];"
        : "=r"(r[0]), "=r"(r[1]), "=r"(r[2]), "=r"(r[3]) : "r"(addr));
}
#define CPA16(dst, src) asm volatile("cp.async.cg.shared.global [%0], [%1], 16;" :: "r"(dst), "l"(src) : "memory")
#define CPA_COMMIT()    asm volatile("cp.async.commit_group;" ::: "memory")
#define CPA_WAIT1()     asm volatile("cp.async.wait_group 1;" ::: "memory")
#define CPA_WAIT0()     asm volatile("cp.async.wait_group 0;" ::: "memory")

// ---------------- structure kernels (fused) ----------------
__device__ __forceinline__ int edge_elem(const int* __restrict__ ei32, int i) {
    return g_is64 ? ei32[2 * i] : ei32[i];
}
__global__ void k_init(const int* __restrict__ ei32) {
    int i = blockIdx.x * blockDim.x + threadIdx.x;
    if (i == 0) {
        int any = 0;
        for (int k = 0; k < 128; k++) any |= ei32[2 * k + 1];
        g_is64 = (any == 0) ? 1 : 0;
    }
    int stride = gridDim.x * blockDim.x;
    for (int j = i; j < Gg * 16384; j += stride) g_ahat[j] = 0.f;
    if (i < Nn) g_deg[i] = 0.f;
    if (i < Gg * 2) g_acc[i] = 0.f;
}
__global__ void k_deg(const int* __restrict__ ei32) {
    int e = blockIdx.x * blockDim.x + threadIdx.x;
    if (e < Ee) {
        int d = edge_elem(ei32, Ee + e);
        if ((unsigned)d < Nn) atomicAdd(&g_deg[d], 1.f);
    }
}
__global__ void k_dinv() {
    int i = blockIdx.x * blockDim.x + threadIdx.x;
    if (i < Nn) g_dinv[i] = rsqrtf(g_deg[i] + 1.f);
}
__global__ void k_scatter(const int* __restrict__ ei32) {
    int idx = blockIdx.x * blockDim.x + threadIdx.x;
    if (idx < Ee) {
        int s = edge_elem(ei32, idx);
        int d = edge_elem(ei32, Ee + idx);
        if ((unsigned)s < Nn && (unsigned)d < Nn) {
            int g = d >> 7;
            atomicAdd(&g_ahat[(g << 14) + ((d & 127) << 7) + (s & 127)],
                      g_dinv[s] * g_dinv[d]);
        }
    } else {
        int i = idx - Ee;
        if (i < Nn) {
            int g = i >> 7, l = i & 127;
            atomicAdd(&g_ahat[(g << 14) + l * 128 + l], g_dinv[i] * g_dinv[i]);
        }
    }
}
// fused converts: ahat -> fp16, X -> fp16, all 4 weight transposes
__global__ void k_split_all(const float* __restrict__ x,
                            const float* __restrict__ W0, const float* __restrict__ W1,
                            const float* __restrict__ W2, const float* __restrict__ W3) {
    int i = blockIdx.x * blockDim.x + threadIdx.x;
    int stride = gridDim.x * blockDim.x;
    for (int j = i; j < Gg * 16384; j += stride)
        g_Ah[j] = __float2half_rn(g_ahat[j]);
    for (int j = i; j < Nn * 256; j += stride)
        g_X[j] = __float2half_rn(x[j]);
    for (int j = i; j < 4 * 65536; j += stride) {
        int w = j >> 16, r = j & 65535;
        int n = r >> 8, k = r & 255;
        const float* W = w == 0 ? W0 : (w == 1 ? W1 : (w == 2 ? W2 : W3));
        g_Wt[j] = __float2half_rn(W[k * 256 + n]);   // Wt[n][k] = W[k][n]
    }
}

// ---------------- pipelined mma GEMM (single-pass fp16, K-chunk 32) ----------------
struct GArg { int aid, bid, oid; const float* bias; int relu; };

#define ST_ROW 80
#define ST_ARR 10240
#define ST_STAGE 20480
#define SMEM_BYTES (2 * ST_STAGE)
#define TROW 136            // fp16 softmax tile row stride (halves)

template <int MODE>
__global__ void __launch_bounds__(256, 2) k_mma(GArg pA, GArg pB,
                                                int aG, int lda, int bG, int ldb, int oG,
                                                const float* __restrict__ Wl) {
    constexpr int KK = (MODE == 0) ? 256 : 128;
    constexpr int NCH = KK / 32;
    extern __shared__ __align__(16) char dynsm[];
    const uint32_t smbase = (uint32_t)__cvta_generic_to_shared(dynsm);

    const int t = threadIdx.x, lane = t & 31, wid = t >> 5;
    const int wr = wid >> 1, wc = wid & 1;
    const int g = blockIdx.x;
    int mb, nb, path;
    if (MODE == 1)      { mb = 0; path = blockIdx.y; nb = blockIdx.z; }
    else if (MODE == 3) { mb = blockIdx.y; nb = blockIdx.z; path = 0; }
    else                { mb = blockIdx.y; path = blockIdx.z; nb = 0; }
    const GArg P = path ? pB : pA;

    const hf* A = bufsel(P.aid) + g * aG + mb * 128 * lda;
    const hf* B = bufsel(P.bid) + g * bG + nb * 128 * ldb;

    const int ldrow = t >> 2, ldseg = t & 3;
    auto issue = [&](int ch) {
        uint32_t sb = smbase + (ch & 1) * ST_STAGE;
#pragma unroll
        for (int i = 0; i < 2; i++) {
            int row = ldrow + i * 64;
            uint32_t dro = row * ST_ROW + ldseg * 16;
            CPA16(sb + dro,          A + row * lda + ch * 32 + ldseg * 8);
            CPA16(sb + ST_ARR + dro, B + row * ldb + ch * 32 + ldseg * 8);
        }
        CPA_COMMIT();
    };

    float acc[2][8][4];
#pragma unroll
    for (int i = 0; i < 2; i++)
#pragma unroll
        for (int j = 0; j < 8; j++)
#pragma unroll
            for (int q = 0; q < 4; q++) acc[i][j][q] = 0.f;

    issue(0);
    const int atile = lane >> 3, arow = lane & 7;
    for (int ch = 0; ch < NCH; ch++) {
        if (ch + 1 < NCH) { issue(ch + 1); CPA_WAIT1(); } else { CPA_WAIT0(); }
        __syncthreads();
        uint32_t sb = smbase + (ch & 1) * ST_STAGE;
#pragma unroll
        for (int ks = 0; ks < 2; ks++) {
            const int k0b = ks * 32;
            uint32_t ah[8];
#pragma unroll
            for (int mt = 0; mt < 2; mt++) {
                uint32_t addr = sb + (wr * 32 + mt * 16 + ((atile & 1) << 3) + arow) * ST_ROW
                                + k0b + ((atile >> 1) << 4);
                ldsm4(ah + mt * 4, addr);
            }
#pragma unroll
            for (int ntp = 0; ntp < 4; ntp++) {
                uint32_t baddr = sb + ST_ARR
                                 + (wc * 64 + ntp * 16 + ((atile >> 1) << 3) + arow) * ST_ROW
                                 + k0b + ((atile & 1) << 4);
                uint32_t bh2[4];
                ldsm4(bh2, baddr);
#pragma unroll
                for (int q2 = 0; q2 < 2; q2++) {
                    int nt = ntp * 2 + q2;
#pragma unroll
                    for (int mt = 0; mt < 2; mt++)
                        mma16816(acc[mt][nt], ah + mt * 4, bh2 + q2 * 2);
                }
            }
        }
        __syncthreads();
    }

    const int gi = lane >> 2, tg = lane & 3;
    // ---------------- epilogues ----------------
    if (MODE == 3) {
        float c0 = 0.f, c1 = 0.f;
        const float2* W2 = (const float2*)Wl;
#pragma unroll
        for (int mt = 0; mt < 2; mt++)
#pragma unroll
            for (int nt = 0; nt < 8; nt++) {
                int d0 = mb * 128 + wr * 32 + mt * 16 + gi;
                int e  = nb * 128 + wc * 64 + nt * 8 + tg * 2;
                float2 w;
                w = __ldg(&W2[d0 * 256 + e]);           c0 += acc[mt][nt][0] * w.x; c1 += acc[mt][nt][0] * w.y;
                w = __ldg(&W2[d0 * 256 + e + 1]);       c0 += acc[mt][nt][1] * w.x; c1 += acc[mt][nt][1] * w.y;
                w = __ldg(&W2[(d0 + 8) * 256 + e]);     c0 += acc[mt][nt][2] * w.x; c1 += acc[mt][nt][2] * w.y;
                w = __ldg(&W2[(d0 + 8) * 256 + e + 1]); c0 += acc[mt][nt][3] * w.x; c1 += acc[mt][nt][3] * w.y;
            }
        float* red = (float*)dynsm;
        red[t] = c0; __syncthreads();
        for (int s = 128; s > 0; s >>= 1) { if (t < s) red[t] += red[t + s]; __syncthreads(); }
        if (t == 0) atomicAdd(&g_acc[g * 2], red[0]);
        __syncthreads();
        red[t] = c1; __syncthreads();
        for (int s = 128; s > 0; s >>= 1) { if (t < s) red[t] += red[t + s]; __syncthreads(); }
        if (t == 0) atomicAdd(&g_acc[g * 2 + 1], red[0]);
        return;
    }

    hf* O;
    int ostride, ocol0;
    if (MODE == 1) { O = bufsel(P.oid) + g * oG; ostride = 256; ocol0 = nb * 128; }
    else           { O = bufsel(P.oid) + g * oG + mb * 16384; ostride = 128; ocol0 = 0; }

    if (MODE == 2 && P.relu == 0) {
        // a-path layer-2 prop: fuse the per-graph node softmax here.
        // Pipeline smem is dead after the mainloop's final __syncthreads().
        hf* tile = (hf*)dynsm;   // 128 x TROW halves = 34 KB < 40 KB
#pragma unroll
        for (int mt = 0; mt < 2; mt++)
#pragma unroll
            for (int nt = 0; nt < 8; nt++) {
                int row0 = wr * 32 + mt * 16 + gi;
                int col  = wc * 64 + nt * 8 + tg * 2;
#pragma unroll
                for (int half = 0; half < 2; half++) {
                    int row = row0 + half * 8;
                    float bb = __ldg(&P.bias[mb * 128 + row]);
                    tile[row * TROW + col]     = __float2half_rn(acc[mt][nt][half * 2] + bb);
                    tile[row * TROW + col + 1] = __float2half_rn(acc[mt][nt][half * 2 + 1] + bb);
                }
            }
        __syncthreads();
        // each warp softmaxes 16 rows over the 128-node axis
#pragma unroll
        for (int i = 0; i < 16; i++) {
            int row = wid * 16 + i;
            float v[4];
#pragma unroll
            for (int j = 0; j < 4; j++)
                v[j] = __half2float(tile[row * TROW + lane * 4 + j]);
            float m = fmaxf(fmaxf(v[0], v[1]), fmaxf(v[2], v[3]));
#pragma unroll
            for (int s = 16; s > 0; s >>= 1) m = fmaxf(m, __shfl_xor_sync(0xFFFFFFFF, m, s));
            float e[4], su = 0.f;
#pragma unroll
            for (int j = 0; j < 4; j++) { e[j] = __expf(v[j] - m); su += e[j]; }
#pragma unroll
            for (int s = 16; s > 0; s >>= 1) su += __shfl_xor_sync(0xFFFFFFFF, su, s);
            float inv = 1.f / su;
            __half2 p0, p1;
            p0.x = __float2half_rn(e[0] * inv); p0.y = __float2half_rn(e[1] * inv);
            p1.x = __float2half_rn(e[2] * inv); p1.y = __float2half_rn(e[3] * inv);
            *(__half2*)(O + row * 128 + lane * 4)     = p0;
            *(__half2*)(O + row * 128 + lane * 4 + 2) = p1;
        }
        return;
    }

#pragma unroll
    for (int mt = 0; mt < 2; mt++)
#pragma unroll
        for (int nt = 0; nt < 8; nt++) {
            int row0 = wr * 32 + mt * 16 + gi;
            int col  = wc * 64 + nt * 8 + tg * 2;
#pragma unroll
            for (int half = 0; half < 2; half++) {
                int row = row0 + half * 8;
                float v0 = acc[mt][nt][half * 2];
                float v1 = acc[mt][nt][half * 2 + 1];
                if (MODE == 1) {
                    v0 += __ldg(&P.bias[ocol0 + col]);
                    v1 += __ldg(&P.bias[ocol0 + col + 1]);
                    if (P.relu) { v0 = fmaxf(v0, 0.f); v1 = fmaxf(v1, 0.f); }
                } else if (MODE == 2) {
                    float bb = __ldg(&P.bias[mb * 128 + row]);
                    v0 += bb; v1 += bb;
                    if (P.relu) { v0 = fmaxf(v0, 0.f); v1 = fmaxf(v1, 0.f); }
                }
                __half2 hp;
                hp.x = __float2half_rn(v0); hp.y = __float2half_rn(v1);
                *(__half2*)(O + row * ostride + ocol0 + col) = hp;
            }
        }
}

// ---------------- final bias + 2-class softmax ----------------
__global__ void k_final(const float* __restrict__ bl, float* __restrict__ out) {
    int g = blockIdx.x * blockDim.x + threadIdx.x;
    if (g < Gg) {
        float a = g_acc[2 * g] + bl[0];
        float b = g_acc[2 * g + 1] + bl[1];
        float m = fmaxf(a, b);
        float ea = __expf(a - m), eb = __expf(b - m);
        float inv = 1.f / (ea + eb);
        out[2 * g] = ea * inv;
        out[2 * g + 1] = eb * inv;
    }
}

// ---------------- launch ----------------
extern "C" void kernel_launch(void* const* d_in, const int* in_sizes, int n_in,
                              void* d_out, int out_size) {
    const float* x    = (const float*)d_in[0];
    const int*   ei32 = (const int*)d_in[1];
    const float* Wa1 = (const float*)d_in[3];
    const float* ba1 = (const float*)d_in[4];
    const float* Wa2 = (const float*)d_in[5];
    const float* ba2 = (const float*)d_in[6];
    const float* Wx1 = (const float*)d_in[7];
    const float* bx1 = (const float*)d_in[8];
    const float* Wx2 = (const float*)d_in[9];
    const float* bx2 = (const float*)d_in[10];
    const float* Wl  = (const float*)d_in[11];
    const float* bl  = (const float*)d_in[12];
    float* out = (float*)d_out;

    static int smem_set = 0;
    if (!smem_set) {
        cudaFuncSetAttribute(k_mma<0>, cudaFuncAttributeMaxDynamicSharedMemorySize, SMEM_BYTES);
        cudaFuncSetAttribute(k_mma<1>, cudaFuncAttributeMaxDynamicSharedMemorySize, SMEM_BYTES);
        cudaFuncSetAttribute(k_mma<2>, cudaFuncAttributeMaxDynamicSharedMemorySize, SMEM_BYTES);
        cudaFuncSetAttribute(k_mma<3>, cudaFuncAttributeMaxDynamicSharedMemorySize, SMEM_BYTES);
        smem_set = 1;
    }

    // structure (fused)
    k_init<<<128, 256>>>(ei32);
    k_deg<<<Ee / 256, 256>>>(ei32);
    k_dinv<<<Nn / 256, 256>>>();
    k_scatter<<<(Ee + Nn) / 256, 256>>>(ei32);

    // converts (single fused kernel)
    k_split_all<<<4096, 256>>>(x, Wa1, Wa2, Wx1, Wx2);

    // ids: 0=X 1=Pa 2=Px 3=Aca 4=Acx 5=Af 6=Xf 7=Ahat; neg = Wt(-1..-4)
    dim3 gq(Gg, 2, 2);
    GArg pa, pb;

    // layer-1 feature GEMMs (both paths)
    pa = {-1, 0, 1, nullptr, 0}; pb = {-3, 0, 2, nullptr, 0};
    k_mma<0><<<gq, 256, SMEM_BYTES>>>(pa, pb, 0, 256, 32768, 256, 32768, nullptr);
    // layer-1 propagation (both paths)
    pa = {7, 1, 3, ba1, 1}; pb = {7, 2, 4, bx1, 1};
    k_mma<1><<<gq, 256, SMEM_BYTES>>>(pa, pb, 16384, 128, 32768, 128, 32768, nullptr);
    // layer-2 feature GEMMs
    pa = {-2, 3, 1, nullptr, 0}; pb = {-4, 4, 2, nullptr, 0};
    k_mma<0><<<gq, 256, SMEM_BYTES>>>(pa, pb, 0, 256, 32768, 256, 32768, nullptr);
    // layer-2 propagation (transposed); a-path (relu=0) does fused softmax
    pa = {1, 7, 5, ba2, 0}; pb = {2, 7, 6, bx2, 1};
    k_mma<2><<<gq, 256, SMEM_BYTES>>>(pa, pb, 32768, 128, 16384, 128, 32768, nullptr);

    // bilinear + head
    pa = {5, 6, 0, nullptr, 0};
    k_mma<3><<<gq, 256, SMEM_BYTES>>>(pa, pa, 32768, 128, 32768, 128, 0, Wl);
    k_final<<<1, 256>>>(bl, out);
}

// round 15
// speedup vs baseline: 1.1387x; 1.0091x over previous
#include <cuda_runtime.h>
#include <cuda_fp16.h>
#include <math.h>
#include <stdint.h>

#define Nn 32768
#define Gg 256
#define Ee 262144

typedef __half hf;

// ---------------- scratch (device globals: no allocation) ----------------
__device__ float g_deg[Nn];
__device__ float g_ahat[Gg * 16384];
__device__ float g_acc[Gg * 2];
__device__ int   g_cnt[Gg];
__device__ int   g_is64;

#define DECLHF(n, sz) __device__ __align__(16) hf n[sz]
DECLHF(g_X,  Nn * 256);
DECLHF(g_Pa, Nn * 256);
DECLHF(g_Px, Nn * 256);
DECLHF(g_Aca, Nn * 256);
DECLHF(g_Acx, Nn * 256);
DECLHF(g_Af, Nn * 256);
DECLHF(g_Xf, Nn * 256);
DECLHF(g_Ah, Gg * 16384);
DECLHF(g_Wt, 4 * 65536);

__device__ __forceinline__ hf* bufsel(int id) {
    switch (id) {
        case 0: return g_X;   case 1: return g_Pa; case 2: return g_Px;
        case 3: return g_Aca; case 4: return g_Acx;
        case 5: return g_Af;  case 6: return g_Xf; case 7: return g_Ah;
    }
    return g_Wt + (-id - 1) * 65536;
}

// ---------------- mma.sync m16n8k16 fp16 ----------------
__device__ __forceinline__ void mma16816(float* c, const uint32_t* a, const uint32_t* b) {
    asm volatile(
        "mma.sync.aligned.m16n8k16.row.col.f32.f16.f16.f32 "
        "{%0,%1,%2,%3}, {%4,%5,%6,%7}, {%8,%9}, {%0,%1,%2,%3};"
        : "+f"(c[0]), "+f"(c[1]), "+f"(c[2]), "+f"(c[3])
        : "r"(a[0]), "r"(a[1]), "r"(a[2]), "r"(a[3]), "r"(b[0]), "r"(b[1]));
}
__device__ __forceinline__ void ldsm4(uint32_t* r, uint32_t addr) {
    asm volatile("ldmatrix.sync.aligned.m8n8.x4.shared.b16 {%0,%1,%2,%3}, [%4];"
        : "=r"(r[0]), "=r"(r[1]), "=r"(r[2]), "=r"(r[3]) : "r"(addr));
}
#define CPA16(dst, src) asm volatile("cp.async.cg.shared.global [%0], [%1], 16;" :: "r"(dst), "l"(src) : "memory")
#define CPA_COMMIT()    asm volatile("cp.async.commit_group;" ::: "memory")
#define CPA_WAIT1()     asm volatile("cp.async.wait_group 1;" ::: "memory")
#define CPA_WAIT0()     asm volatile("cp.async.wait_group 0;" ::: "memory")

// ---------------- structure kernels (fused) ----------------
__device__ __forceinline__ int edge_elem(const int* __restrict__ ei32, int i) {
    return g_is64 ? ei32[2 * i] : ei32[i];
}
__global__ void k_init(const int* __restrict__ ei32) {
    int i = blockIdx.x * blockDim.x + threadIdx.x;
    if (i == 0) {
        int any = 0;
        for (int k = 0; k < 128; k++) any |= ei32[2 * k + 1];
        g_is64 = (any == 0) ? 1 : 0;
    }
    int stride = gridDim.x * blockDim.x;
    for (int j = i; j < Gg * 16384; j += stride) g_ahat[j] = 0.f;
    if (i < Nn) g_deg[i] = 0.f;
    if (i < Gg * 2) g_acc[i] = 0.f;
    if (i < Gg) g_cnt[i] = 0;
}
__global__ void k_deg(const int* __restrict__ ei32) {
    int e = blockIdx.x * blockDim.x + threadIdx.x;
    if (e < Ee) {
        int d = edge_elem(ei32, Ee + e);
        if ((unsigned)d < Nn) atomicAdd(&g_deg[d], 1.f);
    }
}
// scatter with inline dinv = rsqrt(deg+1); plus diagonal term
__global__ void k_scatter(const int* __restrict__ ei32) {
    int idx = blockIdx.x * blockDim.x + threadIdx.x;
    if (idx < Ee) {
        int s = edge_elem(ei32, idx);
        int d = edge_elem(ei32, Ee + idx);
        if ((unsigned)s < Nn && (unsigned)d < Nn) {
            float w = rsqrtf(g_deg[s] + 1.f) * rsqrtf(g_deg[d] + 1.f);
            int g = d >> 7;
            atomicAdd(&g_ahat[(g << 14) + ((d & 127) << 7) + (s & 127)], w);
        }
    } else {
        int i = idx - Ee;
        if (i < Nn) {
            int g = i >> 7, l = i & 127;
            atomicAdd(&g_ahat[(g << 14) + l * 128 + l], __frcp_rn(g_deg[i] + 1.f));
        }
    }
}
// fused converts: ahat -> fp16, X -> fp16, all 4 weight transposes
__global__ void k_split_all(const float* __restrict__ x,
                            const float* __restrict__ W0, const float* __restrict__ W1,
                            const float* __restrict__ W2, const float* __restrict__ W3) {
    int i = blockIdx.x * blockDim.x + threadIdx.x;
    int stride = gridDim.x * blockDim.x;
    for (int j = i; j < Gg * 16384; j += stride)
        g_Ah[j] = __float2half_rn(g_ahat[j]);
    for (int j = i; j < Nn * 256; j += stride)
        g_X[j] = __float2half_rn(x[j]);
    for (int j = i; j < 4 * 65536; j += stride) {
        int w = j >> 16, r = j & 65535;
        int n = r >> 8, k = r & 255;
        const float* W = w == 0 ? W0 : (w == 1 ? W1 : (w == 2 ? W2 : W3));
        g_Wt[j] = __float2half_rn(W[k * 256 + n]);   // Wt[n][k] = W[k][n]
    }
}

// ---------------- pipelined mma GEMM (single-pass fp16, K-chunk 32) ----------------
struct GArg { int aid, bid, oid; const float* bias; int relu; };

#define ST_ROW 80
#define ST_ARR 10240
#define ST_STAGE 20480
#define SMEM_BYTES (2 * ST_STAGE)
#define TROW 136

template <int MODE>
__global__ void __launch_bounds__(256, 2) k_mma(GArg pA, GArg pB,
                                                int aG, int lda, int bG, int ldb, int oG,
                                                const float* __restrict__ Wl,
                                                const float* __restrict__ bl,
                                                float* __restrict__ outp) {
    constexpr int KK = (MODE == 0) ? 256 : 128;
    constexpr int NCH = KK / 32;
    extern __shared__ __align__(16) char dynsm[];
    const uint32_t smbase = (uint32_t)__cvta_generic_to_shared(dynsm);

    const int t = threadIdx.x, lane = t & 31, wid = t >> 5;
    const int wr = wid >> 1, wc = wid & 1;
    const int g = blockIdx.x;
    int mb, nb, path;
    if (MODE == 1)      { mb = 0; path = blockIdx.y; nb = blockIdx.z; }
    else if (MODE == 3) { mb = blockIdx.y; nb = blockIdx.z; path = 0; }
    else                { mb = blockIdx.y; path = blockIdx.z; nb = 0; }
    const GArg P = path ? pB : pA;

    const hf* A = bufsel(P.aid) + g * aG + mb * 128 * lda;
    const hf* B = bufsel(P.bid) + g * bG + nb * 128 * ldb;

    const int ldrow = t >> 2, ldseg = t & 3;
    auto issue = [&](int ch) {
        uint32_t sb = smbase + (ch & 1) * ST_STAGE;
#pragma unroll
        for (int i = 0; i < 2; i++) {
            int row = ldrow + i * 64;
            uint32_t dro = row * ST_ROW + ldseg * 16;
            CPA16(sb + dro,          A + row * lda + ch * 32 + ldseg * 8);
            CPA16(sb + ST_ARR + dro, B + row * ldb + ch * 32 + ldseg * 8);
        }
        CPA_COMMIT();
    };

    float acc[2][8][4];
#pragma unroll
    for (int i = 0; i < 2; i++)
#pragma unroll
        for (int j = 0; j < 8; j++)
#pragma unroll
            for (int q = 0; q < 4; q++) acc[i][j][q] = 0.f;

    issue(0);
    const int atile = lane >> 3, arow = lane & 7;
    for (int ch = 0; ch < NCH; ch++) {
        if (ch + 1 < NCH) { issue(ch + 1); CPA_WAIT1(); } else { CPA_WAIT0(); }
        __syncthreads();
        uint32_t sb = smbase + (ch & 1) * ST_STAGE;
#pragma unroll
        for (int ks = 0; ks < 2; ks++) {
            const int k0b = ks * 32;
            uint32_t ah[8];
#pragma unroll
            for (int mt = 0; mt < 2; mt++) {
                uint32_t addr = sb + (wr * 32 + mt * 16 + ((atile & 1) << 3) + arow) * ST_ROW
                                + k0b + ((atile >> 1) << 4);
                ldsm4(ah + mt * 4, addr);
            }
#pragma unroll
            for (int ntp = 0; ntp < 4; ntp++) {
                uint32_t baddr = sb + ST_ARR
                                 + (wc * 64 + ntp * 16 + ((atile >> 1) << 3) + arow) * ST_ROW
                                 + k0b + ((atile & 1) << 4);
                uint32_t bh2[4];
                ldsm4(bh2, baddr);
#pragma unroll
                for (int q2 = 0; q2 < 2; q2++) {
                    int nt = ntp * 2 + q2;
#pragma unroll
                    for (int mt = 0; mt < 2; mt++)
                        mma16816(acc[mt][nt], ah + mt * 4, bh2 + q2 * 2);
                }
            }
        }
        __syncthreads();
    }

    const int gi = lane >> 2, tg = lane & 3;
    // ---------------- epilogues ----------------
    if (MODE == 3) {
        float c0 = 0.f, c1 = 0.f;
        const float2* W2 = (const float2*)Wl;
#pragma unroll
        for (int mt = 0; mt < 2; mt++)
#pragma unroll
            for (int nt = 0; nt < 8; nt++) {
                int d0 = mb * 128 + wr * 32 + mt * 16 + gi;
                int e  = nb * 128 + wc * 64 + nt * 8 + tg * 2;
                float2 w;
                w = __ldg(&W2[d0 * 256 + e]);           c0 += acc[mt][nt][0] * w.x; c1 += acc[mt][nt][0] * w.y;
                w = __ldg(&W2[d0 * 256 + e + 1]);       c0 += acc[mt][nt][1] * w.x; c1 += acc[mt][nt][1] * w.y;
                w = __ldg(&W2[(d0 + 8) * 256 + e]);     c0 += acc[mt][nt][2] * w.x; c1 += acc[mt][nt][2] * w.y;
                w = __ldg(&W2[(d0 + 8) * 256 + e + 1]); c0 += acc[mt][nt][3] * w.x; c1 += acc[mt][nt][3] * w.y;
            }
        float* red = (float*)dynsm;
        red[t] = c0; __syncthreads();
        for (int s = 128; s > 0; s >>= 1) { if (t < s) red[t] += red[t + s]; __syncthreads(); }
        if (t == 0) atomicAdd(&g_acc[g * 2], red[0]);
        __syncthreads();
        red[t] = c1; __syncthreads();
        for (int s = 128; s > 0; s >>= 1) { if (t < s) red[t] += red[t + s]; __syncthreads(); }
        if (t == 0) {
            atomicAdd(&g_acc[g * 2 + 1], red[0]);
            __threadfence();
            int old = atomicAdd(&g_cnt[g], 1);
            if (old == 3) {   // last CTA for this graph: finish the head here
                float a = g_acc[2 * g] + __ldg(&bl[0]);
                float b = g_acc[2 * g + 1] + __ldg(&bl[1]);
                float m = fmaxf(a, b);
                float ea = __expf(a - m), eb = __expf(b - m);
                float inv = 1.f / (ea + eb);
                outp[2 * g] = ea * inv;
                outp[2 * g + 1] = eb * inv;
            }
        }
        return;
    }

    hf* O;
    int ostride, ocol0;
    if (MODE == 1) { O = bufsel(P.oid) + g * oG; ostride = 256; ocol0 = nb * 128; }
    else           { O = bufsel(P.oid) + g * oG + mb * 16384; ostride = 128; ocol0 = 0; }

    if (MODE == 2 && P.relu == 0) {
        // a-path layer-2 prop: fused per-graph node softmax (pipeline smem is dead)
        hf* tile = (hf*)dynsm;
#pragma unroll
        for (int mt = 0; mt < 2; mt++)
#pragma unroll
            for (int nt = 0; nt < 8; nt++) {
                int row0 = wr * 32 + mt * 16 + gi;
                int col  = wc * 64 + nt * 8 + tg * 2;
#pragma unroll
                for (int half = 0; half < 2; half++) {
                    int row = row0 + half * 8;
                    float bb = __ldg(&P.bias[mb * 128 + row]);
                    tile[row * TROW + col]     = __float2half_rn(acc[mt][nt][half * 2] + bb);
                    tile[row * TROW + col + 1] = __float2half_rn(acc[mt][nt][half * 2 + 1] + bb);
                }
            }
        __syncthreads();
#pragma unroll
        for (int i = 0; i < 16; i++) {
            int row = wid * 16 + i;
            float v[4];
#pragma unroll
            for (int j = 0; j < 4; j++)
                v[j] = __half2float(tile[row * TROW + lane * 4 + j]);
            float m = fmaxf(fmaxf(v[0], v[1]), fmaxf(v[2], v[3]));
#pragma unroll
            for (int s = 16; s > 0; s >>= 1) m = fmaxf(m, __shfl_xor_sync(0xFFFFFFFF, m, s));
            float e[4], su = 0.f;
#pragma unroll
            for (int j = 0; j < 4; j++) { e[j] = __expf(v[j] - m); su += e[j]; }
#pragma unroll
            for (int s = 16; s > 0; s >>= 1) su += __shfl_xor_sync(0xFFFFFFFF, su, s);
            float inv = 1.f / su;
            __half2 p0, p1;
            p0.x = __float2half_rn(e[0] * inv); p0.y = __float2half_rn(e[1] * inv);
            p1.x = __float2half_rn(e[2] * inv); p1.y = __float2half_rn(e[3] * inv);
            *(__half2*)(O + row * 128 + lane * 4)     = p0;
            *(__half2*)(O + row * 128 + lane * 4 + 2) = p1;
        }
        return;
    }

#pragma unroll
    for (int mt = 0; mt < 2; mt++)
#pragma unroll
        for (int nt = 0; nt < 8; nt++) {
            int row0 = wr * 32 + mt * 16 + gi;
            int col  = wc * 64 + nt * 8 + tg * 2;
#pragma unroll
            for (int half = 0; half < 2; half++) {
                int row = row0 + half * 8;
                float v0 = acc[mt][nt][half * 2];
                float v1 = acc[mt][nt][half * 2 + 1];
                if (MODE == 1) {
                    v0 += __ldg(&P.bias[ocol0 + col]);
                    v1 += __ldg(&P.bias[ocol0 + col + 1]);
                    if (P.relu) { v0 = fmaxf(v0, 0.f); v1 = fmaxf(v1, 0.f); }
                } else if (MODE == 2) {
                    float bb = __ldg(&P.bias[mb * 128 + row]);
                    v0 += bb; v1 += bb;
                    if (P.relu) { v0 = fmaxf(v0, 0.f); v1 = fmaxf(v1, 0.f); }
                }
                __half2 hp;
                hp.x = __float2half_rn(v0); hp.y = __float2half_rn(v1);
                *(__half2*)(O + row * ostride + ocol0 + col) = hp;
            }
        }
}

// ---------------- launch ----------------
extern "C" void kernel_launch(void* const* d_in, const int* in_sizes, int n_in,
                              void* d_out, int out_size) {
    const float* x    = (const float*)d_in[0];
    const int*   ei32 = (const int*)d_in[1];
    const float* Wa1 = (const float*)d_in[3];
    const float* ba1 = (const float*)d_in[4];
    const float* Wa2 = (const float*)d_in[5];
    const float* ba2 = (const float*)d_in[6];
    const float* Wx1 = (const float*)d_in[7];
    const float* bx1 = (const float*)d_in[8];
    const float* Wx2 = (const float*)d_in[9];
    const float* bx2 = (const float*)d_in[10];
    const float* Wl  = (const float*)d_in[11];
    const float* bl  = (const float*)d_in[12];
    float* out = (float*)d_out;

    static int smem_set = 0;
    if (!smem_set) {
        cudaFuncSetAttribute(k_mma<0>, cudaFuncAttributeMaxDynamicSharedMemorySize, SMEM_BYTES);
        cudaFuncSetAttribute(k_mma<1>, cudaFuncAttributeMaxDynamicSharedMemorySize, SMEM_BYTES);
        cudaFuncSetAttribute(k_mma<2>, cudaFuncAttributeMaxDynamicSharedMemorySize, SMEM_BYTES);
        cudaFuncSetAttribute(k_mma<3>, cudaFuncAttributeMaxDynamicSharedMemorySize, SMEM_BYTES);
        smem_set = 1;
    }

    // structure (fused; dinv computed inline in scatter)
    k_init<<<128, 256>>>(ei32);
    k_deg<<<Ee / 256, 256>>>(ei32);
    k_scatter<<<(Ee + Nn) / 256, 256>>>(ei32);

    // converts (single fused kernel)
    k_split_all<<<4096, 256>>>(x, Wa1, Wa2, Wx1, Wx2);

    // ids: 0=X 1=Pa 2=Px 3=Aca 4=Acx 5=Af 6=Xf 7=Ahat; neg = Wt(-1..-4)
    dim3 gq(Gg, 2, 2);
    GArg pa, pb;

    // layer-1 feature GEMMs (both paths)
    pa = {-1, 0, 1, nullptr, 0}; pb = {-3, 0, 2, nullptr, 0};
    k_mma<0><<<gq, 256, SMEM_BYTES>>>(pa, pb, 0, 256, 32768, 256, 32768, nullptr, nullptr, nullptr);
    // layer-1 propagation (both paths)
    pa = {7, 1, 3, ba1, 1}; pb = {7, 2, 4, bx1, 1};
    k_mma<1><<<gq, 256, SMEM_BYTES>>>(pa, pb, 16384, 128, 32768, 128, 32768, nullptr, nullptr, nullptr);
    // layer-2 feature GEMMs
    pa = {-2, 3, 1, nullptr, 0}; pb = {-4, 4, 2, nullptr, 0};
    k_mma<0><<<gq, 256, SMEM_BYTES>>>(pa, pb, 0, 256, 32768, 256, 32768, nullptr, nullptr, nullptr);
    // layer-2 propagation (transposed); a-path (relu=0) does fused softmax
    pa = {1, 7, 5, ba2, 0}; pb = {2, 7, 6, bx2, 1};
    k_mma<2><<<gq, 256, SMEM_BYTES>>>(pa, pb, 32768, 128, 16384, 128, 32768, nullptr, nullptr, nullptr);

    // bilinear + fused head (last CTA per graph writes the output softmax)
    pa = {5, 6, 0, nullptr, 0};
    k_mma<3><<<gq, 256, SMEM_BYTES>>>(pa, pa, 32768, 128, 32768, 128, 0, Wl, bl, out);
}

// round 16
// speedup vs baseline: 1.1519x; 1.0116x over previous
#include <cuda_runtime.h>
#include <cuda_fp16.h>
#include <math.h>
#include <stdint.h>

#define Nn 32768
#define Gg 256
#define Ee 262144

typedef __half hf;

// ---------------- scratch (device globals: no allocation) ----------------
__device__ float g_deg[Nn];
__device__ float g_ahat[Gg * 16384];
__device__ float g_acc[Gg * 2];
__device__ int   g_cnt[Gg];
__device__ int   g_is64;

#define DECLHF(n, sz) __device__ __align__(16) hf n[sz]
DECLHF(g_X,  Nn * 256);
DECLHF(g_Pa, Nn * 256);
DECLHF(g_Px, Nn * 256);
DECLHF(g_Aca, Nn * 256);
DECLHF(g_Acx, Nn * 256);
DECLHF(g_Af, Nn * 256);
DECLHF(g_Xf, Nn * 256);
DECLHF(g_Ah, Gg * 16384);
DECLHF(g_Wt, 4 * 65536);

__device__ __forceinline__ hf* bufsel(int id) {
    switch (id) {
        case 0: return g_X;   case 1: return g_Pa; case 2: return g_Px;
        case 3: return g_Aca; case 4: return g_Acx;
        case 5: return g_Af;  case 6: return g_Xf; case 7: return g_Ah;
    }
    return g_Wt + (-id - 1) * 65536;
}

// ---------------- mma.sync m16n8k16 fp16 ----------------
__device__ __forceinline__ void mma16816(float* c, const uint32_t* a, const uint32_t* b) {
    asm volatile(
        "mma.sync.aligned.m16n8k16.row.col.f32.f16.f16.f32 "
        "{%0,%1,%2,%3}, {%4,%5,%6,%7}, {%8,%9}, {%0,%1,%2,%3};"
        : "+f"(c[0]), "+f"(c[1]), "+f"(c[2]), "+f"(c[3])
        : "r"(a[0]), "r"(a[1]), "r"(a[2]), "r"(a[3]), "r"(b[0]), "r"(b[1]));
}
__device__ __forceinline__ void ldsm4(uint32_t* r, uint32_t addr) {
    asm volatile("ldmatrix.sync.aligned.m8n8.x4.shared.b16 {%0,%1,%2,%3}, [%4];"
        : "=r"(r[0]), "=r"(r[1]), "=r"(r[2]), "=r"(r[3]) : "r"(addr));
}
#define CPA16(dst, src) asm volatile("cp.async.cg.shared.global [%0], [%1], 16;" :: "r"(dst), "l"(src) : "memory")
#define CPA_COMMIT()    asm volatile("cp.async.commit_group;" ::: "memory")
#define CPA_WAIT1()     asm volatile("cp.async.wait_group 1;" ::: "memory")
#define CPA_WAIT0()     asm volatile("cp.async.wait_group 0;" ::: "memory")

// ---------------- structure kernels ----------------
__device__ __forceinline__ int edge_elem(const int* __restrict__ ei32, int i) {
    return g_is64 ? ei32[2 * i] : ei32[i];
}
__global__ void k_init(const int* __restrict__ ei32) {
    int i = blockIdx.x * blockDim.x + threadIdx.x;
    if (i == 0) {
        int any = 0;
        for (int k = 0; k < 128; k++) any |= ei32[2 * k + 1];
        g_is64 = (any == 0) ? 1 : 0;
    }
    int stride = gridDim.x * blockDim.x;
    for (int j = i; j < Gg * 16384; j += stride) g_ahat[j] = 0.f;
    if (i < Nn) g_deg[i] = 0.f;
    if (i < Gg * 2) g_acc[i] = 0.f;
    if (i < Gg) g_cnt[i] = 0;
}
__global__ void k_deg(const int* __restrict__ ei32) {
    int e = blockIdx.x * blockDim.x + threadIdx.x;
    if (e < Ee) {
        int d = edge_elem(ei32, Ee + e);
        if ((unsigned)d < Nn) atomicAdd(&g_deg[d], 1.f);
    }
}
__global__ void k_scatter(const int* __restrict__ ei32) {
    int idx = blockIdx.x * blockDim.x + threadIdx.x;
    if (idx < Ee) {
        int s = edge_elem(ei32, idx);
        int d = edge_elem(ei32, Ee + idx);
        if ((unsigned)s < Nn && (unsigned)d < Nn) {
            float w = rsqrtf(g_deg[s] + 1.f) * rsqrtf(g_deg[d] + 1.f);
            int g = d >> 7;
            atomicAdd(&g_ahat[(g << 14) + ((d & 127) << 7) + (s & 127)], w);
        }
    } else {
        int i = idx - Ee;
        if (i < Nn) {
            int g = i >> 7, l = i & 127;
            atomicAdd(&g_ahat[(g << 14) + l * 128 + l], __frcp_rn(g_deg[i] + 1.f));
        }
    }
}
__global__ void k_convAh() {
    int i = blockIdx.x * blockDim.x + threadIdx.x;
    int stride = gridDim.x * blockDim.x;
    for (int j = i; j < Gg * 16384; j += stride)
        g_Ah[j] = __float2half_rn(g_ahat[j]);
}
// X convert (coalesced, vectorized)
__global__ void k_convX(const float* __restrict__ x) {
    int i = blockIdx.x * blockDim.x + threadIdx.x;
    int stride = gridDim.x * blockDim.x;
    for (int j = i; j < Nn * 64; j += stride) {   // float4 granularity
        float4 v = ((const float4*)x)[j];
        __half2 a, b;
        a.x = __float2half_rn(v.x); a.y = __float2half_rn(v.y);
        b.x = __float2half_rn(v.z); b.y = __float2half_rn(v.w);
        ((__half2*)g_X)[j * 2]     = a;
        ((__half2*)g_X)[j * 2 + 1] = b;
    }
}
// tiled coalesced weight transpose: Wt[n][k] = half(W[k][n])
__global__ void k_wtrans(const float* __restrict__ W0, const float* __restrict__ W1,
                         const float* __restrict__ W2, const float* __restrict__ W3) {
    __shared__ float tile[32][33];
    int w = blockIdx.z;
    const float* W = w == 0 ? W0 : (w == 1 ? W1 : (w == 2 ? W2 : W3));
    int nb = blockIdx.x * 32, kb = blockIdx.y * 32;
    int tx = threadIdx.x, ty = threadIdx.y;   // 32 x 8
#pragma unroll
    for (int r = 0; r < 4; r++)
        tile[ty + r * 8][tx] = W[(kb + ty + r * 8) * 256 + nb + tx];   // coalesced in n
    __syncthreads();
#pragma unroll
    for (int r = 0; r < 4; r++)
        g_Wt[w * 65536 + (nb + ty + r * 8) * 256 + kb + tx] =
            __float2half_rn(tile[tx][ty + r * 8]);                     // coalesced in k
}

// ---------------- pipelined mma GEMM (single-pass fp16, K-chunk 32) ----------------
struct GArg { int aid, bid, oid; const float* bias; int relu; };

#define ST_ROW 80
#define ST_ARR 10240
#define ST_STAGE 20480
#define SMEM_BYTES (2 * ST_STAGE)
#define TROW 136

template <int MODE>
__global__ void __launch_bounds__(256, 2) k_mma(GArg pA, GArg pB,
                                                int aG, int lda, int bG, int ldb, int oG,
                                                const float* __restrict__ Wl,
                                                const float* __restrict__ bl,
                                                float* __restrict__ outp) {
    constexpr int KK = (MODE == 0) ? 256 : 128;
    constexpr int NCH = KK / 32;
    extern __shared__ __align__(16) char dynsm[];
    const uint32_t smbase = (uint32_t)__cvta_generic_to_shared(dynsm);

    const int t = threadIdx.x, lane = t & 31, wid = t >> 5;
    const int wr = wid >> 1, wc = wid & 1;
    const int g = blockIdx.x;
    int mb, nb, path;
    if (MODE == 1)      { mb = 0; path = blockIdx.y; nb = blockIdx.z; }
    else if (MODE == 3) { mb = blockIdx.y; nb = blockIdx.z; path = 0; }
    else                { mb = blockIdx.y; path = blockIdx.z; nb = 0; }
    const GArg P = path ? pB : pA;

    const hf* A = bufsel(P.aid) + g * aG + mb * 128 * lda;
    const hf* B = bufsel(P.bid) + g * bG + nb * 128 * ldb;

    const int ldrow = t >> 2, ldseg = t & 3;
    auto issue = [&](int ch) {
        uint32_t sb = smbase + (ch & 1) * ST_STAGE;
#pragma unroll
        for (int i = 0; i < 2; i++) {
            int row = ldrow + i * 64;
            uint32_t dro = row * ST_ROW + ldseg * 16;
            CPA16(sb + dro,          A + row * lda + ch * 32 + ldseg * 8);
            CPA16(sb + ST_ARR + dro, B + row * ldb + ch * 32 + ldseg * 8);
        }
        CPA_COMMIT();
    };

    float acc[2][8][4];
#pragma unroll
    for (int i = 0; i < 2; i++)
#pragma unroll
        for (int j = 0; j < 8; j++)
#pragma unroll
            for (int q = 0; q < 4; q++) acc[i][j][q] = 0.f;

    issue(0);
    const int atile = lane >> 3, arow = lane & 7;
    for (int ch = 0; ch < NCH; ch++) {
        if (ch + 1 < NCH) { issue(ch + 1); CPA_WAIT1(); } else { CPA_WAIT0(); }
        __syncthreads();
        uint32_t sb = smbase + (ch & 1) * ST_STAGE;
#pragma unroll
        for (int ks = 0; ks < 2; ks++) {
            const int k0b = ks * 32;
            uint32_t ah[8];
#pragma unroll
            for (int mt = 0; mt < 2; mt++) {
                uint32_t addr = sb + (wr * 32 + mt * 16 + ((atile & 1) << 3) + arow) * ST_ROW
                                + k0b + ((atile >> 1) << 4);
                ldsm4(ah + mt * 4, addr);
            }
#pragma unroll
            for (int ntp = 0; ntp < 4; ntp++) {
                uint32_t baddr = sb + ST_ARR
                                 + (wc * 64 + ntp * 16 + ((atile >> 1) << 3) + arow) * ST_ROW
                                 + k0b + ((atile & 1) << 4);
                uint32_t bh2[4];
                ldsm4(bh2, baddr);
#pragma unroll
                for (int q2 = 0; q2 < 2; q2++) {
                    int nt = ntp * 2 + q2;
#pragma unroll
                    for (int mt = 0; mt < 2; mt++)
                        mma16816(acc[mt][nt], ah + mt * 4, bh2 + q2 * 2);
                }
            }
        }
        __syncthreads();
    }

    const int gi = lane >> 2, tg = lane & 3;
    // ---------------- epilogues ----------------
    if (MODE == 3) {
        float c0 = 0.f, c1 = 0.f;
        const float2* W2 = (const float2*)Wl;
#pragma unroll
        for (int mt = 0; mt < 2; mt++)
#pragma unroll
            for (int nt = 0; nt < 8; nt++) {
                int d0 = mb * 128 + wr * 32 + mt * 16 + gi;
                int e  = nb * 128 + wc * 64 + nt * 8 + tg * 2;
                float2 w;
                w = __ldg(&W2[d0 * 256 + e]);           c0 += acc[mt][nt][0] * w.x; c1 += acc[mt][nt][0] * w.y;
                w = __ldg(&W2[d0 * 256 + e + 1]);       c0 += acc[mt][nt][1] * w.x; c1 += acc[mt][nt][1] * w.y;
                w = __ldg(&W2[(d0 + 8) * 256 + e]);     c0 += acc[mt][nt][2] * w.x; c1 += acc[mt][nt][2] * w.y;
                w = __ldg(&W2[(d0 + 8) * 256 + e + 1]); c0 += acc[mt][nt][3] * w.x; c1 += acc[mt][nt][3] * w.y;
            }
        float* red = (float*)dynsm;
        red[t] = c0; __syncthreads();
        for (int s = 128; s > 0; s >>= 1) { if (t < s) red[t] += red[t + s]; __syncthreads(); }
        if (t == 0) atomicAdd(&g_acc[g * 2], red[0]);
        __syncthreads();
        red[t] = c1; __syncthreads();
        for (int s = 128; s > 0; s >>= 1) { if (t < s) red[t] += red[t + s]; __syncthreads(); }
        if (t == 0) {
            atomicAdd(&g_acc[g * 2 + 1], red[0]);
            __threadfence();
            int old = atomicAdd(&g_cnt[g], 1);
            if (old == 3) {
                float a = g_acc[2 * g] + __ldg(&bl[0]);
                float b = g_acc[2 * g + 1] + __ldg(&bl[1]);
                float m = fmaxf(a, b);
                float ea = __expf(a - m), eb = __expf(b - m);
                float inv = 1.f / (ea + eb);
                outp[2 * g] = ea * inv;
                outp[2 * g + 1] = eb * inv;
            }
        }
        return;
    }

    hf* O;
    int ostride, ocol0;
    if (MODE == 1) { O = bufsel(P.oid) + g * oG; ostride = 256; ocol0 = nb * 128; }
    else           { O = bufsel(P.oid) + g * oG + mb * 16384; ostride = 128; ocol0 = 0; }

    if (MODE == 2 && P.relu == 0) {
        hf* tile = (hf*)dynsm;
#pragma unroll
        for (int mt = 0; mt < 2; mt++)
#pragma unroll
            for (int nt = 0; nt < 8; nt++) {
                int row0 = wr * 32 + mt * 16 + gi;
                int col  = wc * 64 + nt * 8 + tg * 2;
#pragma unroll
                for (int half = 0; half < 2; half++) {
                    int row = row0 + half * 8;
                    float bb = __ldg(&P.bias[mb * 128 + row]);
                    tile[row * TROW + col]     = __float2half_rn(acc[mt][nt][half * 2] + bb);
                    tile[row * TROW + col + 1] = __float2half_rn(acc[mt][nt][half * 2 + 1] + bb);
                }
            }
        __syncthreads();
#pragma unroll
        for (int i = 0; i < 16; i++) {
            int row = wid * 16 + i;
            float v[4];
#pragma unroll
            for (int j = 0; j < 4; j++)
                v[j] = __half2float(tile[row * TROW + lane * 4 + j]);
            float m = fmaxf(fmaxf(v[0], v[1]), fmaxf(v[2], v[3]));
#pragma unroll
            for (int s = 16; s > 0; s >>= 1) m = fmaxf(m, __shfl_xor_sync(0xFFFFFFFF, m, s));
            float e[4], su = 0.f;
#pragma unroll
            for (int j = 0; j < 4; j++) { e[j] = __expf(v[j] - m); su += e[j]; }
#pragma unroll
            for (int s = 16; s > 0; s >>= 1) su += __shfl_xor_sync(0xFFFFFFFF, su, s);
            float inv = 1.f / su;
            __half2 p0, p1;
            p0.x = __float2half_rn(e[0] * inv); p0.y = __float2half_rn(e[1] * inv);
            p1.x = __float2half_rn(e[2] * inv); p1.y = __float2half_rn(e[3] * inv);
            *(__half2*)(O + row * 128 + lane * 4)     = p0;
            *(__half2*)(O + row * 128 + lane * 4 + 2) = p1;
        }
        return;
    }

#pragma unroll
    for (int mt = 0; mt < 2; mt++)
#pragma unroll
        for (int nt = 0; nt < 8; nt++) {
            int row0 = wr * 32 + mt * 16 + gi;
            int col  = wc * 64 + nt * 8 + tg * 2;
#pragma unroll
            for (int half = 0; half < 2; half++) {
                int row = row0 + half * 8;
                float v0 = acc[mt][nt][half * 2];
                float v1 = acc[mt][nt][half * 2 + 1];
                if (MODE == 1) {
                    v0 += __ldg(&P.bias[ocol0 + col]);
                    v1 += __ldg(&P.bias[ocol0 + col + 1]);
                    if (P.relu) { v0 = fmaxf(v0, 0.f); v1 = fmaxf(v1, 0.f); }
                } else if (MODE == 2) {
                    float bb = __ldg(&P.bias[mb * 128 + row]);
                    v0 += bb; v1 += bb;
                    if (P.relu) { v0 = fmaxf(v0, 0.f); v1 = fmaxf(v1, 0.f); }
                }
                __half2 hp;
                hp.x = __float2half_rn(v0); hp.y = __float2half_rn(v1);
                *(__half2*)(O + row * ostride + ocol0 + col) = hp;
            }
        }
}

// ---------------- launch ----------------
extern "C" void kernel_launch(void* const* d_in, const int* in_sizes, int n_in,
                              void* d_out, int out_size) {
    const float* x    = (const float*)d_in[0];
    const int*   ei32 = (const int*)d_in[1];
    const float* Wa1 = (const float*)d_in[3];
    const float* ba1 = (const float*)d_in[4];
    const float* Wa2 = (const float*)d_in[5];
    const float* ba2 = (const float*)d_in[6];
    const float* Wx1 = (const float*)d_in[7];
    const float* bx1 = (const float*)d_in[8];
    const float* Wx2 = (const float*)d_in[9];
    const float* bx2 = (const float*)d_in[10];
    const float* Wl  = (const float*)d_in[11];
    const float* bl  = (const float*)d_in[12];
    float* out = (float*)d_out;

    static cudaStream_t s1 = nullptr;
    static cudaEvent_t evFork = nullptr, evJoin = nullptr;
    static int once = 0;
    if (!once) {
        cudaFuncSetAttribute(k_mma<0>, cudaFuncAttributeMaxDynamicSharedMemorySize, SMEM_BYTES);
        cudaFuncSetAttribute(k_mma<1>, cudaFuncAttributeMaxDynamicSharedMemorySize, SMEM_BYTES);
        cudaFuncSetAttribute(k_mma<2>, cudaFuncAttributeMaxDynamicSharedMemorySize, SMEM_BYTES);
        cudaFuncSetAttribute(k_mma<3>, cudaFuncAttributeMaxDynamicSharedMemorySize, SMEM_BYTES);
        cudaStreamCreateWithFlags(&s1, cudaStreamNonBlocking);
        cudaEventCreateWithFlags(&evFork, cudaEventDisableTiming);
        cudaEventCreateWithFlags(&evJoin, cudaEventDisableTiming);
        once = 1;
    }

    // fork: structure chain on s1, converts + layer-1 featGEMM on main stream
    cudaEventRecord(evFork, 0);
    cudaStreamWaitEvent(s1, evFork, 0);
    k_init<<<128, 256, 0, s1>>>(ei32);
    k_deg<<<Ee / 256, 256, 0, s1>>>(ei32);
    k_scatter<<<(Ee + Nn) / 256, 256, 0, s1>>>(ei32);
    k_convAh<<<2048, 256, 0, s1>>>();
    cudaEventRecord(evJoin, s1);

    k_wtrans<<<dim3(8, 8, 4), dim3(32, 8)>>>(Wa1, Wa2, Wx1, Wx2);
    k_convX<<<2048, 256>>>(x);

    // ids: 0=X 1=Pa 2=Px 3=Aca 4=Acx 5=Af 6=Xf 7=Ahat; neg = Wt(-1..-4)
    dim3 gq(Gg, 2, 2);
    GArg pa, pb;

    // layer-1 feature GEMMs (needs X + Wt only)
    pa = {-1, 0, 1, nullptr, 0}; pb = {-3, 0, 2, nullptr, 0};
    k_mma<0><<<gq, 256, SMEM_BYTES>>>(pa, pb, 0, 256, 32768, 256, 32768, nullptr, nullptr, nullptr);

    // join: propagation needs Ahat
    cudaStreamWaitEvent(0, evJoin, 0);

    pa = {7, 1, 3, ba1, 1}; pb = {7, 2, 4, bx1, 1};
    k_mma<1><<<gq, 256, SMEM_BYTES>>>(pa, pb, 16384, 128, 32768, 128, 32768, nullptr, nullptr, nullptr);
    pa = {-2, 3, 1, nullptr, 0}; pb = {-4, 4, 2, nullptr, 0};
    k_mma<0><<<gq, 256, SMEM_BYTES>>>(pa, pb, 0, 256, 32768, 256, 32768, nullptr, nullptr, nullptr);
    pa = {1, 7, 5, ba2, 0}; pb = {2, 7, 6, bx2, 1};
    k_mma<2><<<gq, 256, SMEM_BYTES>>>(pa, pb, 32768, 128, 16384, 128, 32768, nullptr, nullptr, nullptr);

    // bilinear + fused head
    pa = {5, 6, 0, nullptr, 0};
    k_mma<3><<<gq, 256, SMEM_BYTES>>>(pa, pa, 32768, 128, 32768, 128, 0, Wl, bl, out);
}